// round 13
// baseline (speedup 1.0000x reference)
#include <cuda_runtime.h>
#include <cuda_bf16.h>
#include <cstdint>

#define NNODES 50000
#define NEDGES 800000
#define NGRAPH 256
#define INC    128
#define HID    256

#define BM 128
#define BN 128
#define BK 32
#define SA 40

// B fragment-layout weight pool (uint4): per weight [K,256]:
// (K/16) kt x 32 n8 x 32 lanes, uint4 = {b0h,b1h,b0l,b1l}
#define W1_0_F 0
#define W2_0_F 8192
#define W1S_F  24576
#define W2S_F  73728
#define WTOT_F 122880

// t in A-fragment layout: 3128 row-tiles x 16 col-tiles x 32 lanes (uint4)
// hi array then lo array
#define RT_TILES 3128
#define TF_LO   ((size_t)RT_TILES * 16 * 32)

static __device__ __align__(16) float g_z[(size_t)NNODES * HID];
static __device__ __align__(16) float g_h[(size_t)NNODES * HID];
static __device__ __align__(16) uint4 g_tf[2 * TF_LO];
static __device__ __align__(16) uint4 g_wf[WTOT_F];
static __device__ unsigned g_flags[2];

__device__ __forceinline__ int ld_idx(const void* p, long long i, bool is64) {
    if (is64) return (int)__ldg(&((const long long*)p)[i]);
    return __ldg(&((const int*)p)[i]);
}

__device__ __forceinline__ void cvt_hilo(float x0, float x1, unsigned& hi, unsigned& lo) {
    unsigned h;
    asm("cvt.rn.bf16x2.f32 %0, %1, %2;" : "=r"(h) : "f"(x1), "f"(x0));
    float f0 = __uint_as_float(h << 16);
    float f1 = __uint_as_float(h & 0xffff0000u);
    float r0 = x0 - f0, r1 = x1 - f1;
    unsigned l;
    asm("cvt.rn.bf16x2.f32 %0, %1, %2;" : "=r"(l) : "f"(r1), "f"(r0));
    hi = h; lo = l;
}

__global__ void k_init_copy(float* __restrict__ out, const float4* __restrict__ x,
                            float4* __restrict__ z) {
    long long tid = (long long)blockIdx.x * blockDim.x + threadIdx.x;
    long long stride = (long long)gridDim.x * blockDim.x;
    if (tid < 2) g_flags[tid] = 0u;
    for (long long i = tid; i < NGRAPH * HID; i += stride) out[i] = 0.f;
    const long long n4 = (long long)NNODES * INC / 4;
    for (long long i = tid; i < n4; i += stride) z[i] = x[i];
}

// dtype detect + weight pre-convert into MMA B-fragment layout
__global__ void k_detect_cvt(const unsigned* __restrict__ ei, const unsigned* __restrict__ ba,
                             const float* __restrict__ w1_0, const float* __restrict__ w2_0,
                             const float* __restrict__ w1s, const float* __restrict__ w2s) {
    long long stride = (long long)gridDim.x * blockDim.x;
    long long tid = (long long)blockIdx.x * blockDim.x + threadIdx.x;
    for (long long j = tid; j < WTOT_F; j += stride) {
        const float* src;
        int u;
        if (j < W2_0_F)      { src = w1_0; u = (int)j; }
        else if (j < W1S_F)  { src = w2_0; u = (int)(j - W2_0_F); }
        else if (j < W2S_F)  { int loc = (int)(j - W1S_F); src = w1s + (loc / 16384) * (HID * HID); u = loc % 16384; }
        else                 { int loc = (int)(j - W2S_F); src = w2s + (loc / 16384) * (HID * HID); u = loc % 16384; }
        int kt = u >> 10, n8 = (u >> 5) & 31, lane = u & 31;
        int n = n8 * 8 + (lane >> 2);
        int k0 = kt * 16 + (lane & 3) * 2;
        float a = __ldg(&src[(long long)k0 * HID + n]);
        float b = __ldg(&src[(long long)(k0 + 1) * HID + n]);
        float c = __ldg(&src[(long long)(k0 + 8) * HID + n]);
        float d = __ldg(&src[(long long)(k0 + 9) * HID + n]);
        unsigned h01, l01, h89, l89;
        cvt_hilo(a, b, h01, l01);
        cvt_hilo(c, d, h89, l89);
        g_wf[j] = make_uint4(h01, h89, l01, l89);
    }
    unsigned acc = 0;
    for (long long w = 2 * tid + 1; w < 2LL * NEDGES; w += 2 * stride) acc |= ei[w];
    if (acc) atomicOr(&g_flags[0], 1u);
    acc = 0;
    for (long long w = 2 * tid + 1; w < NNODES; w += 2 * stride) acc |= ba[w];
    if (acc) atomicOr(&g_flags[1], 1u);
}

__global__ void k_scatter(const float* __restrict__ h, float* __restrict__ z,
                          const void* __restrict__ ei, int lg) {
    bool is64 = (g_flags[0] == 0u);
    long long total = (long long)NEDGES << lg;
    long long stride = (long long)gridDim.x * blockDim.x;
    long long mask = (1LL << lg) - 1;
    for (long long t = (long long)blockIdx.x * blockDim.x + threadIdx.x; t < total; t += stride) {
        long long e = t >> lg;
        int c = (int)(t & mask) * 4;
        int s = ld_idx(ei, e, is64);
        int d = ld_idx(ei, (long long)NEDGES + e, is64);
        const float4 v = *(const float4*)(h + ((long long)s << (lg + 2)) + c);
        float* dp = z + ((long long)d << (lg + 2)) + c;
        asm volatile("red.global.add.v4.f32 [%0], {%1,%2,%3,%4};"
                     :: "l"(dp), "f"(v.x), "f"(v.y), "f"(v.z), "f"(v.w) : "memory");
    }
}

#define MMA1(AREG, BREG, cc)                                                         \
    asm volatile("mma.sync.aligned.m16n8k16.row.col.f32.bf16.bf16.f32 "              \
                 "{%0,%1,%2,%3}, {%4,%5,%6,%7}, {%8,%9}, {%0,%1,%2,%3};"             \
                 : "+f"(cc[0]), "+f"(cc[1]), "+f"(cc[2]), "+f"(cc[3])                \
                 : "r"(AREG[0]), "r"(AREG[1]), "r"(AREG[2]), "r"(AREG[3]),           \
                   "r"(BREG[0]), "r"(BREG[1]))

// GEMM1: tf = frag_pack(relu(A32 @ W + bias)); A via smem, B via fragment LDG
__global__ void __launch_bounds__(256, 2)
k_gemm1(const float* __restrict__ A32, const uint4* __restrict__ Wf,
        const float* __restrict__ bias, uint4* __restrict__ TF, int K) {
    __shared__ __align__(16) unsigned short Ah[BM * SA];
    __shared__ __align__(16) unsigned short Al[BM * SA];
    const int M = NNODES;
    int tid = threadIdx.x;
    int lane = tid & 31, warp = tid >> 5;
    int wm = (warp & 1) * 64, wn = (warp >> 1) * 32;
    int row0 = blockIdx.x * BM, col0 = blockIdx.y * BN;
    int n8base = (col0 + wn) >> 3;
    float c[4][4][4];
#pragma unroll
    for (int mt = 0; mt < 4; mt++)
#pragma unroll
        for (int nt = 0; nt < 4; nt++)
#pragma unroll
            for (int i = 0; i < 4; i++) c[mt][nt][i] = 0.f;

    for (int kt = 0; kt < K; kt += BK) {
#pragma unroll
        for (int i = 0; i < 4; i++) {
            int lin = tid + i * 256;
            int r = lin >> 3, q = lin & 7;
            int gr = row0 + r;
            float4 v = make_float4(0.f, 0.f, 0.f, 0.f);
            if (gr < M) v = *(const float4*)(A32 + (long long)gr * K + kt + q * 4);
            unsigned h0, l0, h1, l1;
            cvt_hilo(v.x, v.y, h0, l0);
            cvt_hilo(v.z, v.w, h1, l1);
            *(uint2*)&Ah[r * SA + q * 4] = make_uint2(h0, h1);
            *(uint2*)&Al[r * SA + q * 4] = make_uint2(l0, l1);
        }
        __syncthreads();
#pragma unroll
        for (int kc = 0; kc < 2; kc++) {
            unsigned ah[4][4], al[4][4], bh[4][2], bl[4][2];
            int ktile = (kt >> 4) + kc;
#pragma unroll
            for (int nt = 0; nt < 4; nt++) {
                uint4 q = __ldg(Wf + (ktile * 32 + n8base + nt) * 32 + lane);
                bh[nt][0] = q.x; bh[nt][1] = q.y;
                bl[nt][0] = q.z; bl[nt][1] = q.w;
            }
            int arow = lane & 15;
            int acol = kc * 16 + (lane >> 4) * 8;
#pragma unroll
            for (int mt = 0; mt < 4; mt++) {
                unsigned sa = (unsigned)__cvta_generic_to_shared(
                    &Ah[(wm + mt * 16 + arow) * SA + acol]);
                asm volatile("ldmatrix.sync.aligned.m8n8.x4.shared.b16 {%0,%1,%2,%3}, [%4];"
                             : "=r"(ah[mt][0]), "=r"(ah[mt][1]), "=r"(ah[mt][2]), "=r"(ah[mt][3])
                             : "r"(sa));
                unsigned sb = (unsigned)__cvta_generic_to_shared(
                    &Al[(wm + mt * 16 + arow) * SA + acol]);
                asm volatile("ldmatrix.sync.aligned.m8n8.x4.shared.b16 {%0,%1,%2,%3}, [%4];"
                             : "=r"(al[mt][0]), "=r"(al[mt][1]), "=r"(al[mt][2]), "=r"(al[mt][3])
                             : "r"(sb));
            }
#pragma unroll
            for (int mt = 0; mt < 4; mt++)
#pragma unroll
                for (int nt = 0; nt < 4; nt++) {
                    float* cc = c[mt][nt];
                    MMA1(ah[mt], bh[nt], cc); MMA1(ah[mt], bl[nt], cc);
                    MMA1(al[mt], bh[nt], cc);
                }
        }
        __syncthreads();
    }

    // Epilogue: write relu(c+bias) as A-fragments (hi + lo arrays)
    int tg = lane & 3;
    unsigned* tfw = (unsigned*)TF;
#pragma unroll
    for (int nt = 0; nt < 4; nt++) {
        int gcol8 = col0 + wn + nt * 8;
        int ct16 = gcol8 >> 4;
        int half = (gcol8 >> 3) & 1;
        float b0 = bias[gcol8 + tg * 2], b1 = bias[gcol8 + tg * 2 + 1];
#pragma unroll
        for (int mt = 0; mt < 4; mt++) {
            int rt = (row0 + wm + mt * 16) >> 4;
            long long base = ((long long)(rt * 16 + ct16) * 32 + lane) * 4 + half * 2;
#pragma unroll
            for (int rh = 0; rh < 2; rh++) {
                float ox = fmaxf(c[mt][nt][rh * 2 + 0] + b0, 0.f);
                float oy = fmaxf(c[mt][nt][rh * 2 + 1] + b1, 0.f);
                unsigned hp, lp;
                cvt_hilo(ox, oy, hp, lp);
                tfw[base + rh] = hp;
                tfw[TF_LO * 4 + base + rh] = lp;
            }
        }
    }
}

// GEMM2: relu(TF @ W + bias); NO shared memory, NO barriers — pure LDG + MMA.
__global__ void __launch_bounds__(256, 2)
k_gemm2(const uint4* __restrict__ TF, const uint4* __restrict__ Wf,
        const float* __restrict__ bias, float* __restrict__ C,
        float* __restrict__ C2, float* __restrict__ pool_out,
        const void* __restrict__ ba, int K) {
    const int M = NNODES;
    int tid = threadIdx.x;
    int lane = tid & 31, warp = tid >> 5;
    int wm = (warp & 1) * 64, wn = (warp >> 1) * 32;
    int row0 = blockIdx.x * BM, col0 = blockIdx.y * BN;
    int n8base = (col0 + wn) >> 3;
    float c[4][4][4];
#pragma unroll
    for (int mt = 0; mt < 4; mt++)
#pragma unroll
        for (int nt = 0; nt < 4; nt++)
#pragma unroll
            for (int i = 0; i < 4; i++) c[mt][nt][i] = 0.f;

    int nk16 = K >> 4;
#pragma unroll 2
    for (int kt16 = 0; kt16 < nk16; kt16++) {
        unsigned ah[4][4], al[4][4], bh[4][2], bl[4][2];
#pragma unroll
        for (int mt = 0; mt < 4; mt++) {
            int rt = (row0 + wm + mt * 16) >> 4;
            const uint4* p = TF + (long long)(rt * 16 + kt16) * 32 + lane;
            uint4 vh = __ldg(p);
            uint4 vl = __ldg(p + TF_LO);
            ah[mt][0] = vh.x; ah[mt][1] = vh.y; ah[mt][2] = vh.z; ah[mt][3] = vh.w;
            al[mt][0] = vl.x; al[mt][1] = vl.y; al[mt][2] = vl.z; al[mt][3] = vl.w;
        }
#pragma unroll
        for (int nt = 0; nt < 4; nt++) {
            uint4 q = __ldg(Wf + (kt16 * 32 + n8base + nt) * 32 + lane);
            bh[nt][0] = q.x; bh[nt][1] = q.y;
            bl[nt][0] = q.z; bl[nt][1] = q.w;
        }
#pragma unroll
        for (int mt = 0; mt < 4; mt++)
#pragma unroll
            for (int nt = 0; nt < 4; nt++) {
                float* cc = c[mt][nt];
                MMA1(ah[mt], bh[nt], cc); MMA1(ah[mt], bl[nt], cc);
                MMA1(al[mt], bh[nt], cc);
            }
    }

    bool is64b = (g_flags[1] == 0u);
    int g = lane >> 2, tg = lane & 3;
#pragma unroll
    for (int nt = 0; nt < 4; nt++) {
        int gcol = col0 + wn + nt * 8 + tg * 2;
        float b0 = bias[gcol], b1 = bias[gcol + 1];
#pragma unroll
        for (int mt = 0; mt < 4; mt++) {
#pragma unroll
            for (int half = 0; half < 2; half++) {
                int rr = row0 + wm + mt * 16 + g + half * 8;
                if (rr < M) {
                    float2 o;
                    o.x = fmaxf(c[mt][nt][half * 2 + 0] + b0, 0.f);
                    o.y = fmaxf(c[mt][nt][half * 2 + 1] + b1, 0.f);
                    if (pool_out) {
                        int gb = ld_idx(ba, rr, is64b);
                        float* dp = pool_out + (long long)gb * HID + gcol;
                        asm volatile("red.global.add.v2.f32 [%0], {%1,%2};"
                                     :: "l"(dp), "f"(o.x), "f"(o.y) : "memory");
                    } else {
                        long long off = (long long)rr * HID + gcol;
                        *(float2*)(C + off) = o;
                        if (C2) *(float2*)(C2 + off) = o;
                    }
                }
            }
        }
    }
}

extern "C" void kernel_launch(void* const* d_in, const int* in_sizes, int n_in,
                              void* d_out, int out_size) {
    const float* x    = (const float*)d_in[0];
    const void*  ei   = d_in[1];
    const void*  ba   = d_in[2];
    const float* w1_0 = (const float*)d_in[3];
    const float* b1_0 = (const float*)d_in[4];
    const float* w2_0 = (const float*)d_in[5];
    const float* b2_0 = (const float*)d_in[6];
    const float* w1s  = (const float*)d_in[7];
    const float* b1s  = (const float*)d_in[8];
    const float* w2s  = (const float*)d_in[9];
    const float* b2s  = (const float*)d_in[10];
    float* out = (float*)d_out;

    float *z, *h;
    uint4 *tf, *wf;
    cudaGetSymbolAddress((void**)&z, g_z);
    cudaGetSymbolAddress((void**)&h, g_h);
    cudaGetSymbolAddress((void**)&tf, g_tf);
    cudaGetSymbolAddress((void**)&wf, g_wf);

    dim3 ggrid((NNODES + BM - 1) / BM, HID / BN);  // (391, 2)

    // ncu captures launch index 3 -> k_gemm1 (layer 0).
    k_init_copy<<<2048, 256>>>(out, (const float4*)x, (float4*)z);              // 0
    k_detect_cvt<<<960, 256>>>((const unsigned*)ei, (const unsigned*)ba,        // 1
                               w1_0, w2_0, w1s, w2s);
    k_scatter<<<4736, 256>>>(x, z, ei, 5);                                      // 2
    k_gemm1<<<ggrid, 256>>>(z, wf + W1_0_F, b1_0, tf, INC);                     // 3 <- profiled
    k_gemm2<<<ggrid, 256>>>(tf, wf + W2_0_F, b2_0, h, z, nullptr, nullptr, HID);

    for (int l = 0; l < 3; l++) {
        k_scatter<<<4736, 256>>>(h, z, ei, 6);
        k_gemm1<<<ggrid, 256>>>(z, wf + W1S_F + l * 16384, b1s + l * HID, tf, HID);
        if (l < 2) {
            k_gemm2<<<ggrid, 256>>>(tf, wf + W2S_F + l * 16384, b2s + l * HID,
                                    h, z, nullptr, nullptr, HID);
        } else {
            k_gemm2<<<ggrid, 256>>>(tf, wf + W2S_F + l * 16384, b2s + l * HID,
                                    nullptr, nullptr, out, ba, HID);
        }
    }
}

// round 14
// speedup vs baseline: 1.0717x; 1.0717x over previous
#include <cuda_runtime.h>
#include <cuda_bf16.h>
#include <cstdint>

#define NNODES 50000
#define NEDGES 800000
#define NGRAPH 256
#define INC    128
#define HID    256

#define BM 128
#define BN 128
#define BK 32
#define SA 40

// B fragment-layout weight pool (uint4): per weight [K,256]:
// (K/16) kt x 32 n8 x 32 lanes, uint4 = {b0h,b1h,b0l,b1l}
#define W1_0_F 0
#define W2_0_F 8192
#define W1S_F  24576
#define W2S_F  73728
#define WTOT_F 122880

// t in A-fragment layout: 3128 row-tiles x 16 col-tiles x 32 lanes (uint4)
// hi array then lo array
#define RT_TILES 3128
#define TF_LO   ((size_t)RT_TILES * 16 * 32)

static __device__ __align__(16) float g_z[(size_t)NNODES * HID];
static __device__ __align__(16) float g_h[(size_t)NNODES * HID];
static __device__ __align__(16) uint4 g_tf[2 * TF_LO];
static __device__ __align__(16) uint4 g_wf[WTOT_F];
static __device__ unsigned g_flags[2];

__device__ __forceinline__ int ld_idx(const void* p, long long i, bool is64) {
    if (is64) return (int)__ldg(&((const long long*)p)[i]);
    return __ldg(&((const int*)p)[i]);
}

__device__ __forceinline__ void cvt_hilo(float x0, float x1, unsigned& hi, unsigned& lo) {
    unsigned h;
    asm("cvt.rn.bf16x2.f32 %0, %1, %2;" : "=r"(h) : "f"(x1), "f"(x0));
    float f0 = __uint_as_float(h << 16);
    float f1 = __uint_as_float(h & 0xffff0000u);
    float r0 = x0 - f0, r1 = x1 - f1;
    unsigned l;
    asm("cvt.rn.bf16x2.f32 %0, %1, %2;" : "=r"(l) : "f"(r1), "f"(r0));
    hi = h; lo = l;
}

__global__ void k_init_copy(float* __restrict__ out, const float4* __restrict__ x,
                            float4* __restrict__ z) {
    long long tid = (long long)blockIdx.x * blockDim.x + threadIdx.x;
    long long stride = (long long)gridDim.x * blockDim.x;
    if (tid < 2) g_flags[tid] = 0u;
    for (long long i = tid; i < NGRAPH * HID; i += stride) out[i] = 0.f;
    const long long n4 = (long long)NNODES * INC / 4;
    for (long long i = tid; i < n4; i += stride) z[i] = x[i];
}

// dtype detect + weight pre-convert into MMA B-fragment layout
__global__ void k_detect_cvt(const unsigned* __restrict__ ei, const unsigned* __restrict__ ba,
                             const float* __restrict__ w1_0, const float* __restrict__ w2_0,
                             const float* __restrict__ w1s, const float* __restrict__ w2s) {
    long long stride = (long long)gridDim.x * blockDim.x;
    long long tid = (long long)blockIdx.x * blockDim.x + threadIdx.x;
    for (long long j = tid; j < WTOT_F; j += stride) {
        const float* src;
        int u;
        if (j < W2_0_F)      { src = w1_0; u = (int)j; }
        else if (j < W1S_F)  { src = w2_0; u = (int)(j - W2_0_F); }
        else if (j < W2S_F)  { int loc = (int)(j - W1S_F); src = w1s + (loc / 16384) * (HID * HID); u = loc % 16384; }
        else                 { int loc = (int)(j - W2S_F); src = w2s + (loc / 16384) * (HID * HID); u = loc % 16384; }
        int kt = u >> 10, n8 = (u >> 5) & 31, lane = u & 31;
        int n = n8 * 8 + (lane >> 2);
        int k0 = kt * 16 + (lane & 3) * 2;
        float a = __ldg(&src[(long long)k0 * HID + n]);
        float b = __ldg(&src[(long long)(k0 + 1) * HID + n]);
        float c = __ldg(&src[(long long)(k0 + 8) * HID + n]);
        float d = __ldg(&src[(long long)(k0 + 9) * HID + n]);
        unsigned h01, l01, h89, l89;
        cvt_hilo(a, b, h01, l01);
        cvt_hilo(c, d, h89, l89);
        g_wf[j] = make_uint4(h01, h89, l01, l89);
    }
    unsigned acc = 0;
    for (long long w = 2 * tid + 1; w < 2LL * NEDGES; w += 2 * stride) acc |= ei[w];
    if (acc) atomicOr(&g_flags[0], 1u);
    acc = 0;
    for (long long w = 2 * tid + 1; w < NNODES; w += 2 * stride) acc |= ba[w];
    if (acc) atomicOr(&g_flags[1], 1u);
}

__global__ void k_scatter(const float* __restrict__ h, float* __restrict__ z,
                          const void* __restrict__ ei, int lg) {
    bool is64 = (g_flags[0] == 0u);
    long long total = (long long)NEDGES << lg;
    long long stride = (long long)gridDim.x * blockDim.x;
    long long mask = (1LL << lg) - 1;
    for (long long t = (long long)blockIdx.x * blockDim.x + threadIdx.x; t < total; t += stride) {
        long long e = t >> lg;
        int c = (int)(t & mask) * 4;
        int s = ld_idx(ei, e, is64);
        int d = ld_idx(ei, (long long)NEDGES + e, is64);
        const float4 v = *(const float4*)(h + ((long long)s << (lg + 2)) + c);
        float* dp = z + ((long long)d << (lg + 2)) + c;
        asm volatile("red.global.add.v4.f32 [%0], {%1,%2,%3,%4};"
                     :: "l"(dp), "f"(v.x), "f"(v.y), "f"(v.z), "f"(v.w) : "memory");
    }
}

#define MMA1(AREG, BREG, cc)                                                         \
    asm volatile("mma.sync.aligned.m16n8k16.row.col.f32.bf16.bf16.f32 "              \
                 "{%0,%1,%2,%3}, {%4,%5,%6,%7}, {%8,%9}, {%0,%1,%2,%3};"             \
                 : "+f"(cc[0]), "+f"(cc[1]), "+f"(cc[2]), "+f"(cc[3])                \
                 : "r"(AREG[0]), "r"(AREG[1]), "r"(AREG[2]), "r"(AREG[3]),           \
                   "r"(BREG[0]), "r"(BREG[1]))

// GEMM1: tf = frag_pack(relu(A32 @ W + bias)); A via smem, B via fragment LDG.
// Epilogue stores ONE uint4 per (mt, ct16) per hi/lo array (coalesced STG.128).
__global__ void __launch_bounds__(256, 2)
k_gemm1(const float* __restrict__ A32, const uint4* __restrict__ Wf,
        const float* __restrict__ bias, uint4* __restrict__ TF, int K) {
    __shared__ __align__(16) unsigned short Ah[BM * SA];
    __shared__ __align__(16) unsigned short Al[BM * SA];
    const int M = NNODES;
    int tid = threadIdx.x;
    int lane = tid & 31, warp = tid >> 5;
    int wm = (warp & 1) * 64, wn = (warp >> 1) * 32;
    int row0 = blockIdx.x * BM, col0 = blockIdx.y * BN;
    int n8base = (col0 + wn) >> 3;
    float c[4][4][4];
#pragma unroll
    for (int mt = 0; mt < 4; mt++)
#pragma unroll
        for (int nt = 0; nt < 4; nt++)
#pragma unroll
            for (int i = 0; i < 4; i++) c[mt][nt][i] = 0.f;

    for (int kt = 0; kt < K; kt += BK) {
#pragma unroll
        for (int i = 0; i < 4; i++) {
            int lin = tid + i * 256;
            int r = lin >> 3, q = lin & 7;
            int gr = row0 + r;
            float4 v = make_float4(0.f, 0.f, 0.f, 0.f);
            if (gr < M) v = *(const float4*)(A32 + (long long)gr * K + kt + q * 4);
            unsigned h0, l0, h1, l1;
            cvt_hilo(v.x, v.y, h0, l0);
            cvt_hilo(v.z, v.w, h1, l1);
            *(uint2*)&Ah[r * SA + q * 4] = make_uint2(h0, h1);
            *(uint2*)&Al[r * SA + q * 4] = make_uint2(l0, l1);
        }
        __syncthreads();
#pragma unroll
        for (int kc = 0; kc < 2; kc++) {
            unsigned ah[4][4], al[4][4], bh[4][2], bl[4][2];
            int ktile = (kt >> 4) + kc;
#pragma unroll
            for (int nt = 0; nt < 4; nt++) {
                uint4 q = __ldg(Wf + (ktile * 32 + n8base + nt) * 32 + lane);
                bh[nt][0] = q.x; bh[nt][1] = q.y;
                bl[nt][0] = q.z; bl[nt][1] = q.w;
            }
            int arow = lane & 15;
            int acol = kc * 16 + (lane >> 4) * 8;
#pragma unroll
            for (int mt = 0; mt < 4; mt++) {
                unsigned sa = (unsigned)__cvta_generic_to_shared(
                    &Ah[(wm + mt * 16 + arow) * SA + acol]);
                asm volatile("ldmatrix.sync.aligned.m8n8.x4.shared.b16 {%0,%1,%2,%3}, [%4];"
                             : "=r"(ah[mt][0]), "=r"(ah[mt][1]), "=r"(ah[mt][2]), "=r"(ah[mt][3])
                             : "r"(sa));
                unsigned sb = (unsigned)__cvta_generic_to_shared(
                    &Al[(wm + mt * 16 + arow) * SA + acol]);
                asm volatile("ldmatrix.sync.aligned.m8n8.x4.shared.b16 {%0,%1,%2,%3}, [%4];"
                             : "=r"(al[mt][0]), "=r"(al[mt][1]), "=r"(al[mt][2]), "=r"(al[mt][3])
                             : "r"(sb));
            }
#pragma unroll
            for (int mt = 0; mt < 4; mt++)
#pragma unroll
                for (int nt = 0; nt < 4; nt++) {
                    float* cc = c[mt][nt];
                    MMA1(ah[mt], bh[nt], cc); MMA1(ah[mt], bl[nt], cc);
                    MMA1(al[mt], bh[nt], cc);
                }
        }
        __syncthreads();
    }

    // Epilogue: relu(c+bias) -> A-fragment uint4 stores (fully coalesced)
    int tg = lane & 3;
#pragma unroll
    for (int ct = 0; ct < 2; ct++) {
        int nt0 = ct * 2, nt1 = ct * 2 + 1;
        int gcol16 = col0 + wn + ct * 16;
        int ct16 = gcol16 >> 4;
        float b00 = bias[gcol16 + tg * 2],     b01 = bias[gcol16 + tg * 2 + 1];
        float b10 = bias[gcol16 + 8 + tg * 2], b11 = bias[gcol16 + 8 + tg * 2 + 1];
#pragma unroll
        for (int mt = 0; mt < 4; mt++) {
            int rt = (row0 + wm + mt * 16) >> 4;
            uint4 hi, lo;
            cvt_hilo(fmaxf(c[mt][nt0][0] + b00, 0.f), fmaxf(c[mt][nt0][1] + b01, 0.f), hi.x, lo.x);
            cvt_hilo(fmaxf(c[mt][nt0][2] + b00, 0.f), fmaxf(c[mt][nt0][3] + b01, 0.f), hi.y, lo.y);
            cvt_hilo(fmaxf(c[mt][nt1][0] + b10, 0.f), fmaxf(c[mt][nt1][1] + b11, 0.f), hi.z, lo.z);
            cvt_hilo(fmaxf(c[mt][nt1][2] + b10, 0.f), fmaxf(c[mt][nt1][3] + b11, 0.f), hi.w, lo.w);
            long long idx = (long long)(rt * 16 + ct16) * 32 + lane;
            TF[idx] = hi;
            TF[idx + TF_LO] = lo;
        }
    }
}

// GEMM2: relu(TF @ W + bias); NO shared memory, NO barriers — pure LDG + MMA.
__global__ void __launch_bounds__(256, 2)
k_gemm2(const uint4* __restrict__ TF, const uint4* __restrict__ Wf,
        const float* __restrict__ bias, float* __restrict__ C,
        float* __restrict__ C2, float* __restrict__ pool_out,
        const void* __restrict__ ba, int K) {
    const int M = NNODES;
    int tid = threadIdx.x;
    int lane = tid & 31, warp = tid >> 5;
    int wm = (warp & 1) * 64, wn = (warp >> 1) * 32;
    int row0 = blockIdx.x * BM, col0 = blockIdx.y * BN;
    int n8base = (col0 + wn) >> 3;
    float c[4][4][4];
#pragma unroll
    for (int mt = 0; mt < 4; mt++)
#pragma unroll
        for (int nt = 0; nt < 4; nt++)
#pragma unroll
            for (int i = 0; i < 4; i++) c[mt][nt][i] = 0.f;

    int nk16 = K >> 4;
#pragma unroll 2
    for (int kt16 = 0; kt16 < nk16; kt16++) {
        unsigned ah[4][4], al[4][4], bh[4][2], bl[4][2];
#pragma unroll
        for (int mt = 0; mt < 4; mt++) {
            int rt = (row0 + wm + mt * 16) >> 4;
            const uint4* p = TF + (long long)(rt * 16 + kt16) * 32 + lane;
            uint4 vh = __ldg(p);
            uint4 vl = __ldg(p + TF_LO);
            ah[mt][0] = vh.x; ah[mt][1] = vh.y; ah[mt][2] = vh.z; ah[mt][3] = vh.w;
            al[mt][0] = vl.x; al[mt][1] = vl.y; al[mt][2] = vl.z; al[mt][3] = vl.w;
        }
#pragma unroll
        for (int nt = 0; nt < 4; nt++) {
            uint4 q = __ldg(Wf + (kt16 * 32 + n8base + nt) * 32 + lane);
            bh[nt][0] = q.x; bh[nt][1] = q.y;
            bl[nt][0] = q.z; bl[nt][1] = q.w;
        }
#pragma unroll
        for (int mt = 0; mt < 4; mt++)
#pragma unroll
            for (int nt = 0; nt < 4; nt++) {
                float* cc = c[mt][nt];
                MMA1(ah[mt], bh[nt], cc); MMA1(ah[mt], bl[nt], cc);
                MMA1(al[mt], bh[nt], cc);
            }
    }

    bool is64b = (g_flags[1] == 0u);
    int g = lane >> 2, tg = lane & 3;
#pragma unroll
    for (int nt = 0; nt < 4; nt++) {
        int gcol = col0 + wn + nt * 8 + tg * 2;
        float b0 = bias[gcol], b1 = bias[gcol + 1];
#pragma unroll
        for (int mt = 0; mt < 4; mt++) {
#pragma unroll
            for (int half = 0; half < 2; half++) {
                int rr = row0 + wm + mt * 16 + g + half * 8;
                if (rr < M) {
                    float2 o;
                    o.x = fmaxf(c[mt][nt][half * 2 + 0] + b0, 0.f);
                    o.y = fmaxf(c[mt][nt][half * 2 + 1] + b1, 0.f);
                    if (pool_out) {
                        int gb = ld_idx(ba, rr, is64b);
                        float* dp = pool_out + (long long)gb * HID + gcol;
                        asm volatile("red.global.add.v2.f32 [%0], {%1,%2};"
                                     :: "l"(dp), "f"(o.x), "f"(o.y) : "memory");
                    } else {
                        long long off = (long long)rr * HID + gcol;
                        *(float2*)(C + off) = o;
                        if (C2) *(float2*)(C2 + off) = o;
                    }
                }
            }
        }
    }
}

extern "C" void kernel_launch(void* const* d_in, const int* in_sizes, int n_in,
                              void* d_out, int out_size) {
    const float* x    = (const float*)d_in[0];
    const void*  ei   = d_in[1];
    const void*  ba   = d_in[2];
    const float* w1_0 = (const float*)d_in[3];
    const float* b1_0 = (const float*)d_in[4];
    const float* w2_0 = (const float*)d_in[5];
    const float* b2_0 = (const float*)d_in[6];
    const float* w1s  = (const float*)d_in[7];
    const float* b1s  = (const float*)d_in[8];
    const float* w2s  = (const float*)d_in[9];
    const float* b2s  = (const float*)d_in[10];
    float* out = (float*)d_out;

    float *z, *h;
    uint4 *tf, *wf;
    cudaGetSymbolAddress((void**)&z, g_z);
    cudaGetSymbolAddress((void**)&h, g_h);
    cudaGetSymbolAddress((void**)&tf, g_tf);
    cudaGetSymbolAddress((void**)&wf, g_wf);

    dim3 ggrid((NNODES + BM - 1) / BM, HID / BN);  // (391, 2)

    // ncu captures launch index 3 -> k_gemm1 (layer 0).
    k_init_copy<<<2048, 256>>>(out, (const float4*)x, (float4*)z);              // 0
    k_detect_cvt<<<960, 256>>>((const unsigned*)ei, (const unsigned*)ba,        // 1
                               w1_0, w2_0, w1s, w2s);
    k_scatter<<<4736, 256>>>(x, z, ei, 5);                                      // 2
    k_gemm1<<<ggrid, 256>>>(z, wf + W1_0_F, b1_0, tf, INC);                     // 3 <- profiled
    k_gemm2<<<ggrid, 256>>>(tf, wf + W2_0_F, b2_0, h, z, nullptr, nullptr, HID);

    for (int l = 0; l < 3; l++) {
        k_scatter<<<4736, 256>>>(h, z, ei, 6);
        k_gemm1<<<ggrid, 256>>>(z, wf + W1S_F + l * 16384, b1s + l * HID, tf, HID);
        if (l < 2) {
            k_gemm2<<<ggrid, 256>>>(tf, wf + W2S_F + l * 16384, b2s + l * HID,
                                    h, z, nullptr, nullptr, HID);
        } else {
            k_gemm2<<<ggrid, 256>>>(tf, wf + W2S_F + l * 16384, b2s + l * HID,
                                    nullptr, nullptr, out, ba, HID);
        }
    }
}

// round 16
// speedup vs baseline: 1.4329x; 1.3370x over previous
#include <cuda_runtime.h>
#include <cuda_bf16.h>
#include <cstdint>

#define NNODES 50000
#define NEDGES 800000
#define NGRAPH 256
#define INC    128
#define HID    256

#define BM 128
#define BN 128
#define BK 32
#define SA 40

// B fragment-layout weight pool (uint4): per weight [K,256]:
// (K/16) kt x 32 n8 x 32 lanes, uint4 = {b0h,b1h,b0l,b1l}
#define W1_0_F 0
#define W2_0_F 8192
#define W1S_F  24576
#define W2S_F  73728
#define WTOT_F 122880

// t in A-fragment layout: 3128 row-tiles x 16 col-tiles x 32 lanes (uint4)
#define RT_TILES 3128
#define TF_LO   ((size_t)RT_TILES * 16 * 32)

static __device__ __align__(16) float g_z[(size_t)NNODES * HID];
static __device__ __align__(16) float g_h[(size_t)NNODES * HID];
static __device__ __align__(16) uint4 g_tf[2 * TF_LO];
static __device__ __align__(16) uint4 g_wf[WTOT_F];
static __device__ unsigned g_flags[2];
// CSR scratch
static __device__ int g_cnt[NNODES];
static __device__ int g_row[NNODES + 1];
static __device__ int g_cur[NNODES];
static __device__ int g_csrc[NEDGES];

__device__ __forceinline__ int ld_idx(const void* p, long long i, bool is64) {
    if (is64) return (int)__ldg(&((const long long*)p)[i]);
    return __ldg(&((const int*)p)[i]);
}

__device__ __forceinline__ void cvt_hilo(float x0, float x1, unsigned& hi, unsigned& lo) {
    unsigned h;
    asm("cvt.rn.bf16x2.f32 %0, %1, %2;" : "=r"(h) : "f"(x1), "f"(x0));
    float f0 = __uint_as_float(h << 16);
    float f1 = __uint_as_float(h & 0xffff0000u);
    float r0 = x0 - f0, r1 = x1 - f1;
    unsigned l;
    asm("cvt.rn.bf16x2.f32 %0, %1, %2;" : "=r"(l) : "f"(r1), "f"(r0));
    hi = h; lo = l;
}

// Launch 0: zero out + flags + counts
__global__ void k_init(float* __restrict__ out) {
    long long tid = (long long)blockIdx.x * blockDim.x + threadIdx.x;
    long long stride = (long long)gridDim.x * blockDim.x;
    if (tid < 2) g_flags[tid] = 0u;
    for (long long i = tid; i < NGRAPH * HID; i += stride) out[i] = 0.f;
    for (long long i = tid; i < NNODES; i += stride) g_cnt[i] = 0;
}

// Launch 1: dtype detect + weight pre-convert into MMA B-fragment layout
__global__ void k_detect_cvt(const unsigned* __restrict__ ei, const unsigned* __restrict__ ba,
                             const float* __restrict__ w1_0, const float* __restrict__ w2_0,
                             const float* __restrict__ w1s, const float* __restrict__ w2s) {
    long long stride = (long long)gridDim.x * blockDim.x;
    long long tid = (long long)blockIdx.x * blockDim.x + threadIdx.x;
    for (long long j = tid; j < WTOT_F; j += stride) {
        const float* src;
        int u;
        if (j < W2_0_F)      { src = w1_0; u = (int)j; }
        else if (j < W1S_F)  { src = w2_0; u = (int)(j - W2_0_F); }
        else if (j < W2S_F)  { int loc = (int)(j - W1S_F); src = w1s + (loc / 16384) * (HID * HID); u = loc % 16384; }
        else                 { int loc = (int)(j - W2S_F); src = w2s + (loc / 16384) * (HID * HID); u = loc % 16384; }
        int kt = u >> 10, n8 = (u >> 5) & 31, lane = u & 31;
        int n = n8 * 8 + (lane >> 2);
        int k0 = kt * 16 + (lane & 3) * 2;
        float a = __ldg(&src[(long long)k0 * HID + n]);
        float b = __ldg(&src[(long long)(k0 + 1) * HID + n]);
        float c = __ldg(&src[(long long)(k0 + 8) * HID + n]);
        float d = __ldg(&src[(long long)(k0 + 9) * HID + n]);
        unsigned h01, l01, h89, l89;
        cvt_hilo(a, b, h01, l01);
        cvt_hilo(c, d, h89, l89);
        g_wf[j] = make_uint4(h01, h89, l01, l89);
    }
    unsigned acc = 0;
    for (long long w = 2 * tid + 1; w < 2LL * NEDGES; w += 2 * stride) acc |= ei[w];
    if (acc) atomicOr(&g_flags[0], 1u);
    acc = 0;
    for (long long w = 2 * tid + 1; w < NNODES; w += 2 * stride) acc |= ba[w];
    if (acc) atomicOr(&g_flags[1], 1u);
}

// Launch 2: histogram of dst
__global__ void k_hist(const void* __restrict__ ei) {
    bool is64 = (g_flags[0] == 0u);
    long long stride = (long long)gridDim.x * blockDim.x;
    for (long long e = (long long)blockIdx.x * blockDim.x + threadIdx.x; e < NEDGES; e += stride) {
        int d = ld_idx(ei, (long long)NEDGES + e, is64);
        atomicAdd(&g_cnt[d], 1);
    }
}

// Launch 3: exclusive prefix scan (single block, 1024 threads)
__global__ void __launch_bounds__(1024) k_scan() {
    __shared__ int sh[1024];
    __shared__ int carry_s;
    int tid = threadIdx.x;
    if (tid == 0) carry_s = 0;
    __syncthreads();
    for (int base = 0; base < NNODES; base += 1024) {
        int idx = base + tid;
        int v = (idx < NNODES) ? g_cnt[idx] : 0;
        sh[tid] = v;
        __syncthreads();
        for (int off = 1; off < 1024; off <<= 1) {
            int t2 = (tid >= off) ? sh[tid - off] : 0;
            __syncthreads();
            sh[tid] += t2;
            __syncthreads();
        }
        int excl = sh[tid] - v;
        int carry = carry_s;
        if (idx < NNODES) {
            g_row[idx] = carry + excl;
            g_cur[idx] = carry + excl;
        }
        __syncthreads();
        if (tid == 1023) carry_s = carry + sh[1023];
        __syncthreads();
    }
    if (tid == 0) g_row[NNODES] = carry_s;
}

// Launch 4: fill CSR src array
__global__ void k_fill(const void* __restrict__ ei) {
    bool is64 = (g_flags[0] == 0u);
    long long stride = (long long)gridDim.x * blockDim.x;
    for (long long e = (long long)blockIdx.x * blockDim.x + threadIdx.x; e < NEDGES; e += stride) {
        int s = ld_idx(ei, e, is64);
        int d = ld_idx(ei, (long long)NEDGES + e, is64);
        int pos = atomicAdd(&g_cur[d], 1);
        g_csrc[pos] = s;
    }
}

// Gather: z[n] = hsrc[n] + sum_{j in row[n]} hsrc[csrc[j]]  (register accumulation)
__global__ void k_gather(const float* __restrict__ hsrc, float* __restrict__ z, int lg) {
    long long total = (long long)NNODES << lg;
    long long stride = (long long)gridDim.x * blockDim.x;
    long long mask = (1LL << lg) - 1;
    int hc4 = 1 << lg;
    const float4* h4 = (const float4*)hsrc;
    for (long long t = (long long)blockIdx.x * blockDim.x + threadIdx.x; t < total; t += stride) {
        int n = (int)(t >> lg);
        int g = (int)(t & mask);
        int start = __ldg(&g_row[n]), end = __ldg(&g_row[n + 1]);
        float4 acc = __ldg(h4 + (long long)n * hc4 + g);
        int j = start;
        for (; j + 1 < end; j += 2) {
            int s0 = __ldg(&g_csrc[j]);
            int s1 = __ldg(&g_csrc[j + 1]);
            float4 v0 = __ldg(h4 + (long long)s0 * hc4 + g);
            float4 v1 = __ldg(h4 + (long long)s1 * hc4 + g);
            acc.x += v0.x + v1.x; acc.y += v0.y + v1.y;
            acc.z += v0.z + v1.z; acc.w += v0.w + v1.w;
        }
        if (j < end) {
            int s0 = __ldg(&g_csrc[j]);
            float4 v0 = __ldg(h4 + (long long)s0 * hc4 + g);
            acc.x += v0.x; acc.y += v0.y; acc.z += v0.z; acc.w += v0.w;
        }
        ((float4*)z)[(long long)n * hc4 + g] = acc;
    }
}

#define MMA1(AREG, BREG, cc)                                                         \
    asm volatile("mma.sync.aligned.m16n8k16.row.col.f32.bf16.bf16.f32 "              \
                 "{%0,%1,%2,%3}, {%4,%5,%6,%7}, {%8,%9}, {%0,%1,%2,%3};"             \
                 : "+f"(cc[0]), "+f"(cc[1]), "+f"(cc[2]), "+f"(cc[3])                \
                 : "r"(AREG[0]), "r"(AREG[1]), "r"(AREG[2]), "r"(AREG[3]),           \
                   "r"(BREG[0]), "r"(BREG[1]))

// GEMM1: tf = frag_pack(relu(A32 @ W + bias)); A via smem, B via fragment LDG.
__global__ void __launch_bounds__(256, 2)
k_gemm1(const float* __restrict__ A32, const uint4* __restrict__ Wf,
        const float* __restrict__ bias, uint4* __restrict__ TF, int K) {
    __shared__ __align__(16) unsigned short Ah[BM * SA];
    __shared__ __align__(16) unsigned short Al[BM * SA];
    const int M = NNODES;
    int tid = threadIdx.x;
    int lane = tid & 31, warp = tid >> 5;
    int wm = (warp & 1) * 64, wn = (warp >> 1) * 32;
    int row0 = blockIdx.x * BM, col0 = blockIdx.y * BN;
    int n8base = (col0 + wn) >> 3;
    float c[4][4][4];
#pragma unroll
    for (int mt = 0; mt < 4; mt++)
#pragma unroll
        for (int nt = 0; nt < 4; nt++)
#pragma unroll
            for (int i = 0; i < 4; i++) c[mt][nt][i] = 0.f;

    for (int kt = 0; kt < K; kt += BK) {
#pragma unroll
        for (int i = 0; i < 4; i++) {
            int lin = tid + i * 256;
            int r = lin >> 3, q = lin & 7;
            int gr = row0 + r;
            float4 v = make_float4(0.f, 0.f, 0.f, 0.f);
            if (gr < M) v = *(const float4*)(A32 + (long long)gr * K + kt + q * 4);
            unsigned h0, l0, h1, l1;
            cvt_hilo(v.x, v.y, h0, l0);
            cvt_hilo(v.z, v.w, h1, l1);
            *(uint2*)&Ah[r * SA + q * 4] = make_uint2(h0, h1);
            *(uint2*)&Al[r * SA + q * 4] = make_uint2(l0, l1);
        }
        __syncthreads();
#pragma unroll
        for (int kc = 0; kc < 2; kc++) {
            unsigned ah[4][4], al[4][4], bh[4][2], bl[4][2];
            int ktile = (kt >> 4) + kc;
#pragma unroll
            for (int nt = 0; nt < 4; nt++) {
                uint4 q = __ldg(Wf + (ktile * 32 + n8base + nt) * 32 + lane);
                bh[nt][0] = q.x; bh[nt][1] = q.y;
                bl[nt][0] = q.z; bl[nt][1] = q.w;
            }
            int arow = lane & 15;
            int acol = kc * 16 + (lane >> 4) * 8;
#pragma unroll
            for (int mt = 0; mt < 4; mt++) {
                unsigned sa = (unsigned)__cvta_generic_to_shared(
                    &Ah[(wm + mt * 16 + arow) * SA + acol]);
                asm volatile("ldmatrix.sync.aligned.m8n8.x4.shared.b16 {%0,%1,%2,%3}, [%4];"
                             : "=r"(ah[mt][0]), "=r"(ah[mt][1]), "=r"(ah[mt][2]), "=r"(ah[mt][3])
                             : "r"(sa));
                unsigned sb = (unsigned)__cvta_generic_to_shared(
                    &Al[(wm + mt * 16 + arow) * SA + acol]);
                asm volatile("ldmatrix.sync.aligned.m8n8.x4.shared.b16 {%0,%1,%2,%3}, [%4];"
                             : "=r"(al[mt][0]), "=r"(al[mt][1]), "=r"(al[mt][2]), "=r"(al[mt][3])
                             : "r"(sb));
            }
#pragma unroll
            for (int mt = 0; mt < 4; mt++)
#pragma unroll
                for (int nt = 0; nt < 4; nt++) {
                    float* cc = c[mt][nt];
                    MMA1(ah[mt], bh[nt], cc); MMA1(ah[mt], bl[nt], cc);
                    MMA1(al[mt], bh[nt], cc);
                }
        }
        __syncthreads();
    }

    // Epilogue: relu(c+bias) -> A-fragment uint4 stores (fully coalesced)
    int tg = lane & 3;
#pragma unroll
    for (int ct = 0; ct < 2; ct++) {
        int nt0 = ct * 2, nt1 = ct * 2 + 1;
        int gcol16 = col0 + wn + ct * 16;
        int ct16 = gcol16 >> 4;
        float b00 = bias[gcol16 + tg * 2],     b01 = bias[gcol16 + tg * 2 + 1];
        float b10 = bias[gcol16 + 8 + tg * 2], b11 = bias[gcol16 + 8 + tg * 2 + 1];
#pragma unroll
        for (int mt = 0; mt < 4; mt++) {
            int rt = (row0 + wm + mt * 16) >> 4;
            uint4 hi, lo;
            cvt_hilo(fmaxf(c[mt][nt0][0] + b00, 0.f), fmaxf(c[mt][nt0][1] + b01, 0.f), hi.x, lo.x);
            cvt_hilo(fmaxf(c[mt][nt0][2] + b00, 0.f), fmaxf(c[mt][nt0][3] + b01, 0.f), hi.y, lo.y);
            cvt_hilo(fmaxf(c[mt][nt1][0] + b10, 0.f), fmaxf(c[mt][nt1][1] + b11, 0.f), hi.z, lo.z);
            cvt_hilo(fmaxf(c[mt][nt1][2] + b10, 0.f), fmaxf(c[mt][nt1][3] + b11, 0.f), hi.w, lo.w);
            long long idx = (long long)(rt * 16 + ct16) * 32 + lane;
            TF[idx] = hi;
            TF[idx + TF_LO] = lo;
        }
    }
}

// GEMM2: relu(TF @ W + bias); NO shared memory, NO barriers — pure LDG + MMA.
__global__ void __launch_bounds__(256, 2)
k_gemm2(const uint4* __restrict__ TF, const uint4* __restrict__ Wf,
        const float* __restrict__ bias, float* __restrict__ C,
        float* __restrict__ pool_out, const void* __restrict__ ba, int K) {
    const int M = NNODES;
    int tid = threadIdx.x;
    int lane = tid & 31, warp = tid >> 5;
    int wm = (warp & 1) * 64, wn = (warp >> 1) * 32;
    int row0 = blockIdx.x * BM, col0 = blockIdx.y * BN;
    int n8base = (col0 + wn) >> 3;
    float c[4][4][4];
#pragma unroll
    for (int mt = 0; mt < 4; mt++)
#pragma unroll
        for (int nt = 0; nt < 4; nt++)
#pragma unroll
            for (int i = 0; i < 4; i++) c[mt][nt][i] = 0.f;

    int nk16 = K >> 4;
#pragma unroll 2
    for (int kt16 = 0; kt16 < nk16; kt16++) {
        unsigned ah[4][4], al[4][4], bh[4][2], bl[4][2];
#pragma unroll
        for (int mt = 0; mt < 4; mt++) {
            int rt = (row0 + wm + mt * 16) >> 4;
            const uint4* p = TF + (long long)(rt * 16 + kt16) * 32 + lane;
            uint4 vh = __ldg(p);
            uint4 vl = __ldg(p + TF_LO);
            ah[mt][0] = vh.x; ah[mt][1] = vh.y; ah[mt][2] = vh.z; ah[mt][3] = vh.w;
            al[mt][0] = vl.x; al[mt][1] = vl.y; al[mt][2] = vl.z; al[mt][3] = vl.w;
        }
#pragma unroll
        for (int nt = 0; nt < 4; nt++) {
            uint4 q = __ldg(Wf + (kt16 * 32 + n8base + nt) * 32 + lane);
            bh[nt][0] = q.x; bh[nt][1] = q.y;
            bl[nt][0] = q.z; bl[nt][1] = q.w;
        }
#pragma unroll
        for (int mt = 0; mt < 4; mt++)
#pragma unroll
            for (int nt = 0; nt < 4; nt++) {
                float* cc = c[mt][nt];
                MMA1(ah[mt], bh[nt], cc); MMA1(ah[mt], bl[nt], cc);
                MMA1(al[mt], bh[nt], cc);
            }
    }

    bool is64b = (g_flags[1] == 0u);
    int g = lane >> 2, tg = lane & 3;
#pragma unroll
    for (int nt = 0; nt < 4; nt++) {
        int gcol = col0 + wn + nt * 8 + tg * 2;
        float b0 = bias[gcol], b1 = bias[gcol + 1];
#pragma unroll
        for (int mt = 0; mt < 4; mt++) {
#pragma unroll
            for (int half = 0; half < 2; half++) {
                int rr = row0 + wm + mt * 16 + g + half * 8;
                if (rr < M) {
                    float2 o;
                    o.x = fmaxf(c[mt][nt][half * 2 + 0] + b0, 0.f);
                    o.y = fmaxf(c[mt][nt][half * 2 + 1] + b1, 0.f);
                    if (pool_out) {
                        int gb = ld_idx(ba, rr, is64b);
                        float* dp = pool_out + (long long)gb * HID + gcol;
                        asm volatile("red.global.add.v2.f32 [%0], {%1,%2};"
                                     :: "l"(dp), "f"(o.x), "f"(o.y) : "memory");
                    } else {
                        long long off = (long long)rr * HID + gcol;
                        *(float2*)(C + off) = o;
                    }
                }
            }
        }
    }
}

extern "C" void kernel_launch(void* const* d_in, const int* in_sizes, int n_in,
                              void* d_out, int out_size) {
    const float* x    = (const float*)d_in[0];
    const void*  ei   = d_in[1];
    const void*  ba   = d_in[2];
    const float* w1_0 = (const float*)d_in[3];
    const float* b1_0 = (const float*)d_in[4];
    const float* w2_0 = (const float*)d_in[5];
    const float* b2_0 = (const float*)d_in[6];
    const float* w1s  = (const float*)d_in[7];
    const float* b1s  = (const float*)d_in[8];
    const float* w2s  = (const float*)d_in[9];
    const float* b2s  = (const float*)d_in[10];
    float* out = (float*)d_out;

    float *z, *h;
    uint4 *tf, *wf;
    cudaGetSymbolAddress((void**)&z, g_z);
    cudaGetSymbolAddress((void**)&h, g_h);
    cudaGetSymbolAddress((void**)&tf, g_tf);
    cudaGetSymbolAddress((void**)&wf, g_wf);

    dim3 ggrid((NNODES + BM - 1) / BM, HID / BN);  // (391, 2)

    k_init<<<256, 256>>>(out);                                                  // 0
    k_detect_cvt<<<960, 256>>>((const unsigned*)ei, (const unsigned*)ba,        // 1
                               w1_0, w2_0, w1s, w2s);
    k_hist<<<1024, 256>>>(ei);                                                  // 2
    k_scan<<<1, 1024>>>();                                                      // 3
    k_fill<<<1024, 256>>>(ei);                                                  // 4

    // Layer 0 (K = 128): z = x + agg(x)
    k_gather<<<6250, 256>>>(x, z, 5);                                           // 5
    k_gemm1<<<ggrid, 256>>>(z, wf + W1_0_F, b1_0, tf, INC);
    k_gemm2<<<ggrid, 256>>>(tf, wf + W2_0_F, b2_0, h, nullptr, nullptr, HID);

    for (int l = 0; l < 3; l++) {
        k_gather<<<12500, 256>>>(h, z, 6);
        k_gemm1<<<ggrid, 256>>>(z, wf + W1S_F + l * 16384, b1s + l * HID, tf, HID);
        if (l < 2) {
            k_gemm2<<<ggrid, 256>>>(tf, wf + W2S_F + l * 16384, b2s + l * HID,
                                    h, nullptr, nullptr, HID);
        } else {
            k_gemm2<<<ggrid, 256>>>(tf, wf + W2S_F + l * 16384, b2s + l * HID,
                                    nullptr, out, ba, HID);
        }
    }
}

// round 17
// speedup vs baseline: 1.5549x; 1.0852x over previous
#include <cuda_runtime.h>
#include <cuda_bf16.h>
#include <cstdint>

#define NNODES 50000
#define NEDGES 800000
#define NGRAPH 256
#define INC    128
#define HID    256

#define BM 128
#define BN 128
#define BK 32
#define SA 40

#define NB_SCAN 49   // ceil(50000/1024)

// B fragment-layout weight pool (uint4): per weight [K,256]:
// (K/16) kt x 32 n8 x 32 lanes, uint4 = {b0h,b1h,b0l,b1l}
#define W1_0_F 0
#define W2_0_F 8192
#define W1S_F  24576
#define W2S_F  73728
#define WTOT_F 122880

// t in A-fragment layout: 3128 row-tiles x 16 col-tiles x 32 lanes (uint4)
#define RT_TILES 3128
#define TF_LO   ((size_t)RT_TILES * 16 * 32)

static __device__ __align__(16) float g_z[(size_t)NNODES * HID];
static __device__ __align__(16) float g_h[(size_t)NNODES * HID];
static __device__ __align__(16) uint4 g_tf[2 * TF_LO];
static __device__ __align__(16) uint4 g_wf[WTOT_F];
static __device__ unsigned g_flags[2];
// CSR scratch
static __device__ int g_cnt[NNODES];
static __device__ int g_row[NNODES + 1];
static __device__ int g_cur[NNODES];
static __device__ int g_csrc[NEDGES];
static __device__ int g_bsum[NB_SCAN];
static __device__ int g_boff[NB_SCAN];

__device__ __forceinline__ int ld_idx(const void* p, long long i, bool is64) {
    if (is64) return (int)__ldg(&((const long long*)p)[i]);
    return __ldg(&((const int*)p)[i]);
}

__device__ __forceinline__ void cvt_hilo(float x0, float x1, unsigned& hi, unsigned& lo) {
    unsigned h;
    asm("cvt.rn.bf16x2.f32 %0, %1, %2;" : "=r"(h) : "f"(x1), "f"(x0));
    float f0 = __uint_as_float(h << 16);
    float f1 = __uint_as_float(h & 0xffff0000u);
    float r0 = x0 - f0, r1 = x1 - f1;
    unsigned l;
    asm("cvt.rn.bf16x2.f32 %0, %1, %2;" : "=r"(l) : "f"(r1), "f"(r0));
    hi = h; lo = l;
}

// Launch 0: zero out + flags + counts
__global__ void k_init(float* __restrict__ out) {
    long long tid = (long long)blockIdx.x * blockDim.x + threadIdx.x;
    long long stride = (long long)gridDim.x * blockDim.x;
    if (tid < 2) g_flags[tid] = 0u;
    for (long long i = tid; i < NGRAPH * HID; i += stride) out[i] = 0.f;
    for (long long i = tid; i < NNODES; i += stride) g_cnt[i] = 0;
}

// Launch 1: dtype detect + weight pre-convert into MMA B-fragment layout
__global__ void k_detect_cvt(const unsigned* __restrict__ ei, const unsigned* __restrict__ ba,
                             const float* __restrict__ w1_0, const float* __restrict__ w2_0,
                             const float* __restrict__ w1s, const float* __restrict__ w2s) {
    long long stride = (long long)gridDim.x * blockDim.x;
    long long tid = (long long)blockIdx.x * blockDim.x + threadIdx.x;
    for (long long j = tid; j < WTOT_F; j += stride) {
        const float* src;
        int u;
        if (j < W2_0_F)      { src = w1_0; u = (int)j; }
        else if (j < W1S_F)  { src = w2_0; u = (int)(j - W2_0_F); }
        else if (j < W2S_F)  { int loc = (int)(j - W1S_F); src = w1s + (loc / 16384) * (HID * HID); u = loc % 16384; }
        else                 { int loc = (int)(j - W2S_F); src = w2s + (loc / 16384) * (HID * HID); u = loc % 16384; }
        int kt = u >> 10, n8 = (u >> 5) & 31, lane = u & 31;
        int n = n8 * 8 + (lane >> 2);
        int k0 = kt * 16 + (lane & 3) * 2;
        float a = __ldg(&src[(long long)k0 * HID + n]);
        float b = __ldg(&src[(long long)(k0 + 1) * HID + n]);
        float c = __ldg(&src[(long long)(k0 + 8) * HID + n]);
        float d = __ldg(&src[(long long)(k0 + 9) * HID + n]);
        unsigned h01, l01, h89, l89;
        cvt_hilo(a, b, h01, l01);
        cvt_hilo(c, d, h89, l89);
        g_wf[j] = make_uint4(h01, h89, l01, l89);
    }
    unsigned acc = 0;
    for (long long w = 2 * tid + 1; w < 2LL * NEDGES; w += 2 * stride) acc |= ei[w];
    if (acc) atomicOr(&g_flags[0], 1u);
    acc = 0;
    for (long long w = 2 * tid + 1; w < NNODES; w += 2 * stride) acc |= ba[w];
    if (acc) atomicOr(&g_flags[1], 1u);
}

// Launch 2: histogram of dst
__global__ void k_hist(const void* __restrict__ ei) {
    bool is64 = (g_flags[0] == 0u);
    long long stride = (long long)gridDim.x * blockDim.x;
    for (long long e = (long long)blockIdx.x * blockDim.x + threadIdx.x; e < NEDGES; e += stride) {
        int d = ld_idx(ei, (long long)NEDGES + e, is64);
        atomicAdd(&g_cnt[d], 1);
    }
}

// Hierarchical scan: phase 1 — per-block exclusive scan + block totals
__global__ void __launch_bounds__(1024) k_scan1() {
    __shared__ int sh[1024];
    int tid = threadIdx.x;
    int idx = blockIdx.x * 1024 + tid;
    int v = (idx < NNODES) ? g_cnt[idx] : 0;
    sh[tid] = v;
    __syncthreads();
    for (int off = 1; off < 1024; off <<= 1) {
        int t2 = (tid >= off) ? sh[tid - off] : 0;
        __syncthreads();
        sh[tid] += t2;
        __syncthreads();
    }
    if (idx < NNODES) g_row[idx] = sh[tid] - v;
    if (tid == 1023) g_bsum[blockIdx.x] = sh[1023];
}

// phase 2 — serial scan of block totals (49 values)
__global__ void k_scan2() {
    if (threadIdx.x == 0 && blockIdx.x == 0) {
        int acc = 0;
        for (int i = 0; i < NB_SCAN; i++) { g_boff[i] = acc; acc += g_bsum[i]; }
        g_row[NNODES] = acc;
    }
}

// phase 3 — add block offsets, write row + cur
__global__ void __launch_bounds__(1024) k_scan3() {
    int idx = blockIdx.x * 1024 + threadIdx.x;
    if (idx < NNODES) {
        int r = g_row[idx] + g_boff[blockIdx.x];
        g_row[idx] = r;
        g_cur[idx] = r;
    }
}

// Launch: fill CSR src array
__global__ void k_fill(const void* __restrict__ ei) {
    bool is64 = (g_flags[0] == 0u);
    long long stride = (long long)gridDim.x * blockDim.x;
    for (long long e = (long long)blockIdx.x * blockDim.x + threadIdx.x; e < NEDGES; e += stride) {
        int s = ld_idx(ei, e, is64);
        int d = ld_idx(ei, (long long)NEDGES + e, is64);
        int pos = atomicAdd(&g_cur[d], 1);
        g_csrc[pos] = s;
    }
}

// Gather: z[n] = hsrc[n] + sum_{j in row[n]} hsrc[csrc[j]]  (register accumulation)
__global__ void k_gather(const float* __restrict__ hsrc, float* __restrict__ z, int lg) {
    long long total = (long long)NNODES << lg;
    long long stride = (long long)gridDim.x * blockDim.x;
    long long mask = (1LL << lg) - 1;
    int hc4 = 1 << lg;
    const float4* h4 = (const float4*)hsrc;
    for (long long t = (long long)blockIdx.x * blockDim.x + threadIdx.x; t < total; t += stride) {
        int n = (int)(t >> lg);
        int g = (int)(t & mask);
        int start = __ldg(&g_row[n]), end = __ldg(&g_row[n + 1]);
        float4 acc = __ldg(h4 + (long long)n * hc4 + g);
        int j = start;
        for (; j + 1 < end; j += 2) {
            int s0 = __ldg(&g_csrc[j]);
            int s1 = __ldg(&g_csrc[j + 1]);
            float4 v0 = __ldg(h4 + (long long)s0 * hc4 + g);
            float4 v1 = __ldg(h4 + (long long)s1 * hc4 + g);
            acc.x += v0.x + v1.x; acc.y += v0.y + v1.y;
            acc.z += v0.z + v1.z; acc.w += v0.w + v1.w;
        }
        if (j < end) {
            int s0 = __ldg(&g_csrc[j]);
            float4 v0 = __ldg(h4 + (long long)s0 * hc4 + g);
            acc.x += v0.x; acc.y += v0.y; acc.z += v0.z; acc.w += v0.w;
        }
        ((float4*)z)[(long long)n * hc4 + g] = acc;
    }
}

#define MMA1(AREG, BREG, cc)                                                         \
    asm volatile("mma.sync.aligned.m16n8k16.row.col.f32.bf16.bf16.f32 "              \
                 "{%0,%1,%2,%3}, {%4,%5,%6,%7}, {%8,%9}, {%0,%1,%2,%3};"             \
                 : "+f"(cc[0]), "+f"(cc[1]), "+f"(cc[2]), "+f"(cc[3])                \
                 : "r"(AREG[0]), "r"(AREG[1]), "r"(AREG[2]), "r"(AREG[3]),           \
                   "r"(BREG[0]), "r"(BREG[1]))

// GEMM1: tf = frag_pack(relu(A32 @ W + bias)); A via smem, B via fragment LDG.
__global__ void __launch_bounds__(256, 2)
k_gemm1(const float* __restrict__ A32, const uint4* __restrict__ Wf,
        const float* __restrict__ bias, uint4* __restrict__ TF, int K) {
    __shared__ __align__(16) unsigned short Ah[BM * SA];
    __shared__ __align__(16) unsigned short Al[BM * SA];
    const int M = NNODES;
    int tid = threadIdx.x;
    int lane = tid & 31, warp = tid >> 5;
    int wm = (warp & 1) * 64, wn = (warp >> 1) * 32;
    int row0 = blockIdx.x * BM, col0 = blockIdx.y * BN;
    int n8base = (col0 + wn) >> 3;
    float c[4][4][4];
#pragma unroll
    for (int mt = 0; mt < 4; mt++)
#pragma unroll
        for (int nt = 0; nt < 4; nt++)
#pragma unroll
            for (int i = 0; i < 4; i++) c[mt][nt][i] = 0.f;

    for (int kt = 0; kt < K; kt += BK) {
#pragma unroll
        for (int i = 0; i < 4; i++) {
            int lin = tid + i * 256;
            int r = lin >> 3, q = lin & 7;
            int gr = row0 + r;
            float4 v = make_float4(0.f, 0.f, 0.f, 0.f);
            if (gr < M) v = *(const float4*)(A32 + (long long)gr * K + kt + q * 4);
            unsigned h0, l0, h1, l1;
            cvt_hilo(v.x, v.y, h0, l0);
            cvt_hilo(v.z, v.w, h1, l1);
            *(uint2*)&Ah[r * SA + q * 4] = make_uint2(h0, h1);
            *(uint2*)&Al[r * SA + q * 4] = make_uint2(l0, l1);
        }
        __syncthreads();
#pragma unroll
        for (int kc = 0; kc < 2; kc++) {
            unsigned ah[4][4], al[4][4], bh[4][2], bl[4][2];
            int ktile = (kt >> 4) + kc;
#pragma unroll
            for (int nt = 0; nt < 4; nt++) {
                uint4 q = __ldg(Wf + (ktile * 32 + n8base + nt) * 32 + lane);
                bh[nt][0] = q.x; bh[nt][1] = q.y;
                bl[nt][0] = q.z; bl[nt][1] = q.w;
            }
            int arow = lane & 15;
            int acol = kc * 16 + (lane >> 4) * 8;
#pragma unroll
            for (int mt = 0; mt < 4; mt++) {
                unsigned sa = (unsigned)__cvta_generic_to_shared(
                    &Ah[(wm + mt * 16 + arow) * SA + acol]);
                asm volatile("ldmatrix.sync.aligned.m8n8.x4.shared.b16 {%0,%1,%2,%3}, [%4];"
                             : "=r"(ah[mt][0]), "=r"(ah[mt][1]), "=r"(ah[mt][2]), "=r"(ah[mt][3])
                             : "r"(sa));
                unsigned sb = (unsigned)__cvta_generic_to_shared(
                    &Al[(wm + mt * 16 + arow) * SA + acol]);
                asm volatile("ldmatrix.sync.aligned.m8n8.x4.shared.b16 {%0,%1,%2,%3}, [%4];"
                             : "=r"(al[mt][0]), "=r"(al[mt][1]), "=r"(al[mt][2]), "=r"(al[mt][3])
                             : "r"(sb));
            }
#pragma unroll
            for (int mt = 0; mt < 4; mt++)
#pragma unroll
                for (int nt = 0; nt < 4; nt++) {
                    float* cc = c[mt][nt];
                    MMA1(ah[mt], bh[nt], cc); MMA1(ah[mt], bl[nt], cc);
                    MMA1(al[mt], bh[nt], cc);
                }
        }
        __syncthreads();
    }

    // Epilogue: relu(c+bias) -> A-fragment uint4 stores (fully coalesced)
    int tg = lane & 3;
#pragma unroll
    for (int ct = 0; ct < 2; ct++) {
        int nt0 = ct * 2, nt1 = ct * 2 + 1;
        int gcol16 = col0 + wn + ct * 16;
        int ct16 = gcol16 >> 4;
        float b00 = bias[gcol16 + tg * 2],     b01 = bias[gcol16 + tg * 2 + 1];
        float b10 = bias[gcol16 + 8 + tg * 2], b11 = bias[gcol16 + 8 + tg * 2 + 1];
#pragma unroll
        for (int mt = 0; mt < 4; mt++) {
            int rt = (row0 + wm + mt * 16) >> 4;
            uint4 hi, lo;
            cvt_hilo(fmaxf(c[mt][nt0][0] + b00, 0.f), fmaxf(c[mt][nt0][1] + b01, 0.f), hi.x, lo.x);
            cvt_hilo(fmaxf(c[mt][nt0][2] + b00, 0.f), fmaxf(c[mt][nt0][3] + b01, 0.f), hi.y, lo.y);
            cvt_hilo(fmaxf(c[mt][nt1][0] + b10, 0.f), fmaxf(c[mt][nt1][1] + b11, 0.f), hi.z, lo.z);
            cvt_hilo(fmaxf(c[mt][nt1][2] + b10, 0.f), fmaxf(c[mt][nt1][3] + b11, 0.f), hi.w, lo.w);
            long long idx = (long long)(rt * 16 + ct16) * 32 + lane;
            TF[idx] = hi;
            TF[idx + TF_LO] = lo;
        }
    }
}

// GEMM2: relu(TF @ W + bias); NO shared memory, NO barriers — pure LDG + MMA.
__global__ void __launch_bounds__(256, 2)
k_gemm2(const uint4* __restrict__ TF, const uint4* __restrict__ Wf,
        const float* __restrict__ bias, float* __restrict__ C,
        float* __restrict__ pool_out, const void* __restrict__ ba, int K) {
    const int M = NNODES;
    int tid = threadIdx.x;
    int lane = tid & 31, warp = tid >> 5;
    int wm = (warp & 1) * 64, wn = (warp >> 1) * 32;
    int row0 = blockIdx.x * BM, col0 = blockIdx.y * BN;
    int n8base = (col0 + wn) >> 3;
    float c[4][4][4];
#pragma unroll
    for (int mt = 0; mt < 4; mt++)
#pragma unroll
        for (int nt = 0; nt < 4; nt++)
#pragma unroll
            for (int i = 0; i < 4; i++) c[mt][nt][i] = 0.f;

    int nk16 = K >> 4;
#pragma unroll 2
    for (int kt16 = 0; kt16 < nk16; kt16++) {
        unsigned ah[4][4], al[4][4], bh[4][2], bl[4][2];
#pragma unroll
        for (int mt = 0; mt < 4; mt++) {
            int rt = (row0 + wm + mt * 16) >> 4;
            const uint4* p = TF + (long long)(rt * 16 + kt16) * 32 + lane;
            uint4 vh = __ldg(p);
            uint4 vl = __ldg(p + TF_LO);
            ah[mt][0] = vh.x; ah[mt][1] = vh.y; ah[mt][2] = vh.z; ah[mt][3] = vh.w;
            al[mt][0] = vl.x; al[mt][1] = vl.y; al[mt][2] = vl.z; al[mt][3] = vl.w;
        }
#pragma unroll
        for (int nt = 0; nt < 4; nt++) {
            uint4 q = __ldg(Wf + (kt16 * 32 + n8base + nt) * 32 + lane);
            bh[nt][0] = q.x; bh[nt][1] = q.y;
            bl[nt][0] = q.z; bl[nt][1] = q.w;
        }
#pragma unroll
        for (int mt = 0; mt < 4; mt++)
#pragma unroll
            for (int nt = 0; nt < 4; nt++) {
                float* cc = c[mt][nt];
                MMA1(ah[mt], bh[nt], cc); MMA1(ah[mt], bl[nt], cc);
                MMA1(al[mt], bh[nt], cc);
            }
    }

    bool is64b = (g_flags[1] == 0u);
    int g = lane >> 2, tg = lane & 3;
#pragma unroll
    for (int nt = 0; nt < 4; nt++) {
        int gcol = col0 + wn + nt * 8 + tg * 2;
        float b0 = bias[gcol], b1 = bias[gcol + 1];
#pragma unroll
        for (int mt = 0; mt < 4; mt++) {
#pragma unroll
            for (int half = 0; half < 2; half++) {
                int rr = row0 + wm + mt * 16 + g + half * 8;
                if (rr < M) {
                    float2 o;
                    o.x = fmaxf(c[mt][nt][half * 2 + 0] + b0, 0.f);
                    o.y = fmaxf(c[mt][nt][half * 2 + 1] + b1, 0.f);
                    if (pool_out) {
                        int gb = ld_idx(ba, rr, is64b);
                        float* dp = pool_out + (long long)gb * HID + gcol;
                        asm volatile("red.global.add.v2.f32 [%0], {%1,%2};"
                                     :: "l"(dp), "f"(o.x), "f"(o.y) : "memory");
                    } else {
                        long long off = (long long)rr * HID + gcol;
                        *(float2*)(C + off) = o;
                    }
                }
            }
        }
    }
}

extern "C" void kernel_launch(void* const* d_in, const int* in_sizes, int n_in,
                              void* d_out, int out_size) {
    const float* x    = (const float*)d_in[0];
    const void*  ei   = d_in[1];
    const void*  ba   = d_in[2];
    const float* w1_0 = (const float*)d_in[3];
    const float* b1_0 = (const float*)d_in[4];
    const float* w2_0 = (const float*)d_in[5];
    const float* b2_0 = (const float*)d_in[6];
    const float* w1s  = (const float*)d_in[7];
    const float* b1s  = (const float*)d_in[8];
    const float* w2s  = (const float*)d_in[9];
    const float* b2s  = (const float*)d_in[10];
    float* out = (float*)d_out;

    float *z, *h;
    uint4 *tf, *wf;
    cudaGetSymbolAddress((void**)&z, g_z);
    cudaGetSymbolAddress((void**)&h, g_h);
    cudaGetSymbolAddress((void**)&tf, g_tf);
    cudaGetSymbolAddress((void**)&wf, g_wf);

    dim3 ggrid((NNODES + BM - 1) / BM, HID / BN);  // (391, 2)

    k_init<<<256, 256>>>(out);
    k_detect_cvt<<<960, 256>>>((const unsigned*)ei, (const unsigned*)ba,
                               w1_0, w2_0, w1s, w2s);
    k_hist<<<1024, 256>>>(ei);
    k_scan1<<<NB_SCAN, 1024>>>();
    k_scan2<<<1, 32>>>();
    k_scan3<<<NB_SCAN, 1024>>>();
    k_fill<<<1024, 256>>>(ei);

    // Layer 0 (K = 128): z = x + agg(x)
    k_gather<<<6250, 256>>>(x, z, 5);
    k_gemm1<<<ggrid, 256>>>(z, wf + W1_0_F, b1_0, tf, INC);
    k_gemm2<<<ggrid, 256>>>(tf, wf + W2_0_F, b2_0, h, nullptr, nullptr, HID);

    for (int l = 0; l < 3; l++) {
        k_gather<<<12500, 256>>>(h, z, 6);
        k_gemm1<<<ggrid, 256>>>(z, wf + W1S_F + l * 16384, b1s + l * HID, tf, HID);
        if (l < 2) {
            k_gemm2<<<ggrid, 256>>>(tf, wf + W2S_F + l * 16384, b2s + l * HID,
                                    h, nullptr, nullptr, HID);
        } else {
            k_gemm2<<<ggrid, 256>>>(tf, wf + W2S_F + l * 16384, b2s + l * HID,
                                    nullptr, out, ba, HID);
        }
    }
}